// round 3
// baseline (speedup 1.0000x reference)
#include <cuda_runtime.h>
#include <cstdint>

// CapsuleLayer: v = routing(reshape(x @ W, [B,16,32]))
//   x: [32768, 512] f32, W: [512, 512] f32, out v: [32768, 32] f32
//
// Kernel 1: fp32-accurate GEMM via 3-term TF32 split (Markidis):
//           u = hi(x)hi(W) + hi(x)lo(W) + lo(x)hi(W)  -> __device__ scratch
//           hi/lo interleaved as float2 in smem -> LDS.64 fragment loads.
// Kernel 2: warp-per-row dynamic routing (3 iters) -> out

#define K_DIM 512
#define N_DIM 512
#define NUM_CAPS 16
#define OUT_DIM 32

#define BM 128
#define BN 128
#define BK 8
#define XS_STRIDE (BM + 4)   // in float2 units
#define WS_STRIDE (BN + 4)   // in float2 units
#define MAX_BATCH 32768

// 64 MB scratch for u (__device__ global, no allocation)
__device__ float g_u[(size_t)MAX_BATCH * N_DIM];

__device__ __forceinline__ float f2tf32(float x) {
    uint32_t u;
    asm("cvt.rna.tf32.f32 %0, %1;" : "=r"(u) : "f"(x));
    return __uint_as_float(u);
}

__device__ __forceinline__ float2 split_tf32(float x) {
    float h = f2tf32(x);
    float l = f2tf32(x - h);
    return make_float2(h, l);
}

__device__ __forceinline__ void mma_m16n8k8_tf32(float d[4], const uint32_t a[4],
                                                 const uint32_t b[2]) {
    asm volatile(
        "mma.sync.aligned.m16n8k8.row.col.f32.tf32.tf32.f32 "
        "{%0,%1,%2,%3}, {%4,%5,%6,%7}, {%8,%9}, {%0,%1,%2,%3};\n"
        : "+f"(d[0]), "+f"(d[1]), "+f"(d[2]), "+f"(d[3])
        : "r"(a[0]), "r"(a[1]), "r"(a[2]), "r"(a[3]), "r"(b[0]), "r"(b[1]));
}

// ---------------------------------------------------------------------------
// GEMM: C[M,512] = X[M,512] @ W[512,512], fp32-accurate via TF32 split.
// Block tile 128x128, K-chunk 8, 256 threads (8 warps as 4(m) x 2(n)),
// warp tile 32x64 = 2(m16) x 8(n8) fragments. (hi,lo) float2 in smem.
// ---------------------------------------------------------------------------
__global__ void __launch_bounds__(256, 2)
capsule_gemm_kernel(const float* __restrict__ X, const float* __restrict__ W) {
    __shared__ __align__(16) float2 Xs[2][BK][XS_STRIDE];   // 16.9 KB
    __shared__ __align__(16) float2 Ws[2][BK][WS_STRIDE];   // 16.9 KB

    const int tid = threadIdx.x;
    const int n0 = blockIdx.x * BN;   // n fast-varying -> X tile L2 reuse
    const int m0 = blockIdx.y * BM;

    const int warp = tid >> 5;
    const int lane = tid & 31;
    const int wm = warp >> 1;         // 0..3 -> 32 rows
    const int wn = warp & 1;          // 0..1 -> 64 cols
    const int g = lane >> 2;          // 0..7
    const int t = lane & 3;           // 0..3

    // staging: X tile 128x8 (1 float4/thread), W tile 8x128 (1 float4/thread)
    const int xr  = tid >> 1;         // 0..127
    const int xk  = (tid & 1) << 2;   // 0 or 4
    const int wk  = tid >> 5;         // 0..7
    const int wn4 = (tid & 31) << 2;  // 0..124

    float acc[2][8][4];
#pragma unroll
    for (int i = 0; i < 2; i++)
#pragma unroll
        for (int j = 0; j < 8; j++)
#pragma unroll
            for (int q = 0; q < 4; q++) acc[i][j][q] = 0.f;

    const float* Xbase = X + (size_t)m0 * K_DIM;
    const float* Wbase = W + n0;

    float4 xv, wv;

    auto ldg_tiles = [&](int kb) {
        xv = *reinterpret_cast<const float4*>(Xbase + (size_t)xr * K_DIM + kb + xk);
        wv = *reinterpret_cast<const float4*>(Wbase + (size_t)(kb + wk) * N_DIM + wn4);
    };

    auto sts_tiles = [&](int buf) {
        Xs[buf][xk + 0][xr] = split_tf32(xv.x);
        Xs[buf][xk + 1][xr] = split_tf32(xv.y);
        Xs[buf][xk + 2][xr] = split_tf32(xv.z);
        Xs[buf][xk + 3][xr] = split_tf32(xv.w);
        Ws[buf][wk][wn4 + 0] = split_tf32(wv.x);
        Ws[buf][wk][wn4 + 1] = split_tf32(wv.y);
        Ws[buf][wk][wn4 + 2] = split_tf32(wv.z);
        Ws[buf][wk][wn4 + 3] = split_tf32(wv.w);
    };

    auto compute = [&](int buf) {
        uint32_t aH[2][4], aL[2][4];
#pragma unroll
        for (int i = 0; i < 2; i++) {
            const int mr = wm * 32 + i * 16 + g;
            float2 a0 = Xs[buf][t][mr];
            float2 a1 = Xs[buf][t][mr + 8];
            float2 a2 = Xs[buf][t + 4][mr];
            float2 a3 = Xs[buf][t + 4][mr + 8];
            aH[i][0] = __float_as_uint(a0.x); aL[i][0] = __float_as_uint(a0.y);
            aH[i][1] = __float_as_uint(a1.x); aL[i][1] = __float_as_uint(a1.y);
            aH[i][2] = __float_as_uint(a2.x); aL[i][2] = __float_as_uint(a2.y);
            aH[i][3] = __float_as_uint(a3.x); aL[i][3] = __float_as_uint(a3.y);
        }
#pragma unroll
        for (int j = 0; j < 8; j++) {
            const int nc = wn * 64 + j * 8 + g;
            float2 b0 = Ws[buf][t][nc];
            float2 b1 = Ws[buf][t + 4][nc];
            uint32_t bH[2], bL[2];
            bH[0] = __float_as_uint(b0.x); bL[0] = __float_as_uint(b0.y);
            bH[1] = __float_as_uint(b1.x); bL[1] = __float_as_uint(b1.y);
#pragma unroll
            for (int i = 0; i < 2; i++) {
                mma_m16n8k8_tf32(acc[i][j], aH[i], bH);  // hi*hi
                mma_m16n8k8_tf32(acc[i][j], aH[i], bL);  // hi*lo
                mma_m16n8k8_tf32(acc[i][j], aL[i], bH);  // lo*hi
            }
        }
    };

    // software pipeline: LDG(next) -> compute(cur) -> STS(next) -> barrier
    ldg_tiles(0);
    sts_tiles(0);
    __syncthreads();

    const int NKT = K_DIM / BK;  // 64
    for (int kt = 0; kt < NKT; kt++) {
        const int buf = kt & 1;
        if (kt + 1 < NKT) ldg_tiles((kt + 1) * BK);
        compute(buf);
        if (kt + 1 < NKT) sts_tiles(buf ^ 1);
        __syncthreads();
    }

    // epilogue -> g_u
#pragma unroll
    for (int i = 0; i < 2; i++) {
#pragma unroll
        for (int j = 0; j < 8; j++) {
            const int row = m0 + wm * 32 + i * 16 + g;
            const int col = n0 + wn * 64 + j * 8 + t * 2;
            *reinterpret_cast<float2*>(&g_u[(size_t)row * N_DIM + col]) =
                make_float2(acc[i][j][0], acc[i][j][1]);
            *reinterpret_cast<float2*>(&g_u[(size_t)(row + 8) * N_DIM + col]) =
                make_float2(acc[i][j][2], acc[i][j][3]);
        }
    }
}

// ---------------------------------------------------------------------------
// Routing: one warp per batch row. lane = output dim d (0..31).
// ---------------------------------------------------------------------------
__global__ void __launch_bounds__(256)
capsule_routing_kernel(float* __restrict__ out, int batch) {
    const int gw = (int)((blockIdx.x * blockDim.x + threadIdx.x) >> 5);
    const int lane = threadIdx.x & 31;
    if (gw >= batch) return;

    const float* urow = g_u + (size_t)gw * N_DIM;
    float u[NUM_CAPS];
#pragma unroll
    for (int c = 0; c < NUM_CAPS; c++) u[c] = urow[c * OUT_DIM + lane];

    float b[NUM_CAPS];
#pragma unroll
    for (int c = 0; c < NUM_CAPS; c++) b[c] = 0.f;

    float v = 0.f;
#pragma unroll
    for (int it = 0; it < 3; it++) {
        // softmax over capsules (replicated per lane)
        float mx = b[0];
#pragma unroll
        for (int c = 1; c < NUM_CAPS; c++) mx = fmaxf(mx, b[c]);
        float e[NUM_CAPS], sum = 0.f;
#pragma unroll
        for (int c = 0; c < NUM_CAPS; c++) {
            e[c] = __expf(b[c] - mx);
            sum += e[c];
        }
        const float inv = 1.f / sum;

        // s[lane] = sum_c softmax(b)[c] * u[c][lane]
        float s = 0.f;
#pragma unroll
        for (int c = 0; c < NUM_CAPS; c++) s = fmaf(e[c] * inv, u[c], s);

        // squash: warp allreduce of ||s||^2 over 32 dims
        float norm = s * s;
#pragma unroll
        for (int o = 16; o; o >>= 1) norm += __shfl_xor_sync(0xffffffffu, norm, o);
        const float vscale = (norm / (1.f + norm)) / (sqrtf(norm) + 1e-8f);
        v = vscale * s;

        // b update (skip last iter: unused)
        if (it < 2) {
#pragma unroll
            for (int c = 0; c < NUM_CAPS; c++) {
                float p = u[c] * v;
#pragma unroll
                for (int o = 16; o; o >>= 1) p += __shfl_xor_sync(0xffffffffu, p, o);
                b[c] += p;
            }
        }
    }

    out[(size_t)gw * OUT_DIM + lane] = v;
}

// ---------------------------------------------------------------------------
extern "C" void kernel_launch(void* const* d_in, const int* in_sizes, int n_in,
                              void* d_out, int out_size) {
    const float* X = (const float*)d_in[0];   // [batch, 512]
    const float* W = (const float*)d_in[1];   // [512, 512]
    float* out = (float*)d_out;               // [batch, 32]

    const int batch = in_sizes[0] / K_DIM;    // 32768

    dim3 ggrid(N_DIM / BN, batch / BM);       // (4, 256)
    capsule_gemm_kernel<<<ggrid, 256>>>(X, W);

    const int rthreads = batch * 32;
    capsule_routing_kernel<<<(rthreads + 255) / 256, 256>>>(out, batch);
}

// round 5
// speedup vs baseline: 1.6606x; 1.6606x over previous
#include <cuda_runtime.h>
#include <cuda_fp16.h>
#include <cstdint>

// CapsuleLayer: v = routing(reshape(x @ W, [B,16,32]))
//   x: [32768, 512] f32, W: [512, 512] f32, out v: [32768, 32] f32
//
// Kernel 1: fp32-accurate GEMM via 3-term FP16 split (same 11-bit mantissa as
//           TF32, but m16n8k16 -> half the MMA instructions):
//           u = hi(x)hi(W) + hi(x)lo(W) + lo(x)hi(W)  -> g_u scratch
//           smem holds (hi_half2, lo_half2) uint2 -> one LDS.64 per fragment reg.
// Kernel 2: warp-per-row dynamic routing (3 iters) -> out

#define K_DIM 512
#define N_DIM 512
#define NUM_CAPS 16
#define OUT_DIM 32
#define MAX_BATCH 32768

#define BM 128
#define BN 128
#define BK 16
#define NKP (BK / 2)          // 8 k-pairs per stage
#define XS_STRIDE (BM + 4)
#define WS_STRIDE (BN + 4)

// 64 MB scratch for u (__device__ global, no allocation)
__device__ float g_u[(size_t)MAX_BATCH * N_DIM];

// split x into (hi, lo) fp16 pair: hi = rn16(x), lo = rn16(x - hi)
__device__ __forceinline__ void split16(float x, __half& h, __half& l) {
    h = __float2half_rn(x);
    l = __float2half_rn(x - __half2float(h));
}

// pack two k-adjacent values (v0 = even k -> low half) into (hi2, lo2)
__device__ __forceinline__ uint2 pack_pair(float v0, float v1) {
    __half h0, l0, h1, l1;
    split16(v0, h0, l0);
    split16(v1, h1, l1);
    uint2 r;
    __half2 hh = __halves2half2(h0, h1);
    __half2 ll = __halves2half2(l0, l1);
    r.x = *reinterpret_cast<uint32_t*>(&hh);
    r.y = *reinterpret_cast<uint32_t*>(&ll);
    return r;
}

__device__ __forceinline__ void mma_m16n8k16_f16(float d[4], const uint32_t a[4],
                                                 const uint32_t b[2]) {
    asm volatile(
        "mma.sync.aligned.m16n8k16.row.col.f32.f16.f16.f32 "
        "{%0,%1,%2,%3}, {%4,%5,%6,%7}, {%8,%9}, {%0,%1,%2,%3};\n"
        : "+f"(d[0]), "+f"(d[1]), "+f"(d[2]), "+f"(d[3])
        : "r"(a[0]), "r"(a[1]), "r"(a[2]), "r"(a[3]), "r"(b[0]), "r"(b[1]));
}

// ---------------------------------------------------------------------------
// GEMM: C[M,512] = X[M,512] @ W[512,512], fp32-accurate via FP16 split.
// Block tile 128x128, K-chunk 16, 256 threads (8 warps as 4(m) x 2(n)),
// warp tile 32x64 = 2(m16) x 8(n8) fragments, m16n8k16 HMMA.
// Smem: uint2 (hi2, lo2) indexed [kpair][m] / [kpair][n].
// ---------------------------------------------------------------------------
__global__ void __launch_bounds__(256, 2)
capsule_gemm_kernel(const float* __restrict__ X, const float* __restrict__ W) {
    __shared__ __align__(16) uint2 Xs[2][NKP][XS_STRIDE];   // 16.9 KB
    __shared__ __align__(16) uint2 Ws[2][NKP][WS_STRIDE];   // 16.9 KB

    const int tid = threadIdx.x;
    const int n0 = blockIdx.x * BN;   // n fast-varying -> X tile L2 reuse
    const int m0 = blockIdx.y * BM;

    const int warp = tid >> 5;
    const int lane = tid & 31;
    const int wm = warp >> 1;         // 0..3 -> 32 rows
    const int wn = warp & 1;          // 0..1 -> 64 cols
    const int g = lane >> 2;          // 0..7
    const int t = lane & 3;           // 0..3

    // A staging: row xr (0..127), 8 consecutive k at offset xk8 (0 or 8)
    const int xr  = tid >> 1;
    const int xk8 = (tid & 1) << 3;
    // B staging: k-pair wkp (0..7) covers rows 2wkp, 2wkp+1; cols wn4..wn4+3
    const int wkp = tid >> 5;
    const int wn4 = (tid & 31) << 2;

    float acc[2][8][4];
#pragma unroll
    for (int i = 0; i < 2; i++)
#pragma unroll
        for (int j = 0; j < 8; j++)
#pragma unroll
            for (int q = 0; q < 4; q++) acc[i][j][q] = 0.f;

    const float* Xrow = X + (size_t)(m0 + xr) * K_DIM + xk8;
    const float* Wr0 = W + (size_t)(2 * wkp + 0) * N_DIM + n0 + wn4;
    const float* Wr1 = W + (size_t)(2 * wkp + 1) * N_DIM + n0 + wn4;

    float4 xv0, xv1, wv0, wv1;

    auto ldg_tiles = [&](int kb) {
        xv0 = *reinterpret_cast<const float4*>(Xrow + kb);
        xv1 = *reinterpret_cast<const float4*>(Xrow + kb + 4);
        wv0 = *reinterpret_cast<const float4*>(Wr0 + (size_t)kb * N_DIM);
        wv1 = *reinterpret_cast<const float4*>(Wr1 + (size_t)kb * N_DIM);
    };

    auto sts_tiles = [&](int buf) {
        const int p0 = xk8 >> 1;  // 0 or 4
        Xs[buf][p0 + 0][xr] = pack_pair(xv0.x, xv0.y);
        Xs[buf][p0 + 1][xr] = pack_pair(xv0.z, xv0.w);
        Xs[buf][p0 + 2][xr] = pack_pair(xv1.x, xv1.y);
        Xs[buf][p0 + 3][xr] = pack_pair(xv1.z, xv1.w);
        // B pair combines two k-rows at same n
        Ws[buf][wkp][wn4 + 0] = pack_pair(wv0.x, wv1.x);
        Ws[buf][wkp][wn4 + 1] = pack_pair(wv0.y, wv1.y);
        Ws[buf][wkp][wn4 + 2] = pack_pair(wv0.z, wv1.z);
        Ws[buf][wkp][wn4 + 3] = pack_pair(wv0.w, wv1.w);
    };

    auto compute = [&](int buf) {
        // A fragments: a0={m=g, kp=t} a1={g+8, t} a2={g, t+4} a3={g+8, t+4}
        uint32_t aH[2][4], aL[2][4];
#pragma unroll
        for (int i = 0; i < 2; i++) {
            const int mr = wm * 32 + i * 16 + g;
            uint2 A0 = Xs[buf][t][mr];
            uint2 A1 = Xs[buf][t][mr + 8];
            uint2 A2 = Xs[buf][t + 4][mr];
            uint2 A3 = Xs[buf][t + 4][mr + 8];
            aH[i][0] = A0.x; aL[i][0] = A0.y;
            aH[i][1] = A1.x; aL[i][1] = A1.y;
            aH[i][2] = A2.x; aL[i][2] = A2.y;
            aH[i][3] = A3.x; aL[i][3] = A3.y;
        }
#pragma unroll
        for (int j = 0; j < 8; j++) {
            // B fragments: b0={kp=t, n=g} b1={kp=t+4, n=g}
            const int nc = wn * 64 + j * 8 + g;
            uint2 B0 = Ws[buf][t][nc];
            uint2 B1 = Ws[buf][t + 4][nc];
            uint32_t bH[2] = {B0.x, B1.x};
            uint32_t bL[2] = {B0.y, B1.y};
#pragma unroll
            for (int i = 0; i < 2; i++) {
                mma_m16n8k16_f16(acc[i][j], aH[i], bH);  // hi*hi
                mma_m16n8k16_f16(acc[i][j], aH[i], bL);  // hi*lo
                mma_m16n8k16_f16(acc[i][j], aL[i], bH);  // lo*hi
            }
        }
    };

    // software pipeline: LDG(next) -> compute(cur) -> STS(next) -> barrier
    ldg_tiles(0);
    sts_tiles(0);
    __syncthreads();

    const int NKT = K_DIM / BK;  // 32
    for (int kt = 0; kt < NKT; kt++) {
        const int buf = kt & 1;
        if (kt + 1 < NKT) ldg_tiles((kt + 1) * BK);
        compute(buf);
        if (kt + 1 < NKT) sts_tiles(buf ^ 1);
        __syncthreads();
    }

    // epilogue -> g_u
#pragma unroll
    for (int i = 0; i < 2; i++) {
#pragma unroll
        for (int j = 0; j < 8; j++) {
            const int row = m0 + wm * 32 + i * 16 + g;
            const int col = n0 + wn * 64 + j * 8 + t * 2;
            *reinterpret_cast<float2*>(&g_u[(size_t)row * N_DIM + col]) =
                make_float2(acc[i][j][0], acc[i][j][1]);
            *reinterpret_cast<float2*>(&g_u[(size_t)(row + 8) * N_DIM + col]) =
                make_float2(acc[i][j][2], acc[i][j][3]);
        }
    }
}

// ---------------------------------------------------------------------------
// Routing: one warp per batch row. lane = output dim d (0..31).
// ---------------------------------------------------------------------------
__global__ void __launch_bounds__(256)
capsule_routing_kernel(float* __restrict__ out, int batch) {
    const int gw = (int)((blockIdx.x * blockDim.x + threadIdx.x) >> 5);
    const int lane = threadIdx.x & 31;
    if (gw >= batch) return;

    const float* urow = g_u + (size_t)gw * N_DIM;
    float u[NUM_CAPS];
#pragma unroll
    for (int c = 0; c < NUM_CAPS; c++) u[c] = urow[c * OUT_DIM + lane];

    float b[NUM_CAPS];
#pragma unroll
    for (int c = 0; c < NUM_CAPS; c++) b[c] = 0.f;

    float v = 0.f;
#pragma unroll
    for (int it = 0; it < 3; it++) {
        float mx = b[0];
#pragma unroll
        for (int c = 1; c < NUM_CAPS; c++) mx = fmaxf(mx, b[c]);
        float e[NUM_CAPS], sum = 0.f;
#pragma unroll
        for (int c = 0; c < NUM_CAPS; c++) {
            e[c] = __expf(b[c] - mx);
            sum += e[c];
        }
        const float inv = 1.f / sum;

        float s = 0.f;
#pragma unroll
        for (int c = 0; c < NUM_CAPS; c++) s = fmaf(e[c] * inv, u[c], s);

        float norm = s * s;
#pragma unroll
        for (int o = 16; o; o >>= 1) norm += __shfl_xor_sync(0xffffffffu, norm, o);
        const float vscale = (norm / (1.f + norm)) / (sqrtf(norm) + 1e-8f);
        v = vscale * s;

        if (it < 2) {
#pragma unroll
            for (int c = 0; c < NUM_CAPS; c++) {
                float p = u[c] * v;
#pragma unroll
                for (int o = 16; o; o >>= 1) p += __shfl_xor_sync(0xffffffffu, p, o);
                b[c] += p;
            }
        }
    }

    out[(size_t)gw * OUT_DIM + lane] = v;
}

// ---------------------------------------------------------------------------
extern "C" void kernel_launch(void* const* d_in, const int* in_sizes, int n_in,
                              void* d_out, int out_size) {
    const float* X = (const float*)d_in[0];   // [batch, 512]
    const float* W = (const float*)d_in[1];   // [512, 512]
    float* out = (float*)d_out;               // [batch, 32]

    const int batch = in_sizes[0] / K_DIM;    // 32768

    dim3 ggrid(N_DIM / BN, batch / BM);       // (4, 256)
    capsule_gemm_kernel<<<ggrid, 256>>>(X, W);

    const int rthreads = batch * 32;
    capsule_routing_kernel<<<(rthreads + 255) / 256, 256>>>(out, batch);
}